// round 16
// baseline (speedup 1.0000x reference)
#include <cuda_runtime.h>
#include <cstdint>

// Problem constants
constexpr int B_   = 8;
constexpr int H_   = 8;
constexpr int LQ_  = 1024;
constexpr int LM_  = 4096;
constexpr int DM_  = 512;
constexpr int DK_  = 64;
constexpr int TOPK_ = 32;

// Attention kernel tiling
constexpr int QT   = 64;    // queries per block (8 rows per warp)
constexpr int CK   = 128;   // key chunk cached in smem (32 KB)

// Scratch (static device arrays: allocation-free)
__device__ float g_q[B_*H_*LQ_*DK_];   // 16 MB  [B,H,LQ,Dk]
__device__ float g_k[B_*H_*LM_*DK_];   // 64 MB  [B,H,LM,Dk]
__device__ float g_v[B_*H_*LM_*DK_];   // 64 MB  [B,H,LM,Dk]
__device__ float g_x[B_*LQ_*DM_];      // 16 MB  [B,LQ,DM] pre-output-proj

// ---------------- attention smem layout (float units) ----------------------
// qp: 32 row-pairs x 64 dims, f32x2 packed (2048 ull = 16 KB)
// ks: K chunk 128x64, xor-swizzled float4 (32 KB)
constexpr int OFF_QP  = 0;                  // 4096 floats (2048 ull)
constexpr int OFF_KS  = OFF_QP + 4096;      // 8192 floats
constexpr int SMEM_FLOATS = OFF_KS + CK*DK_;
constexpr int SMEM_BYTES  = SMEM_FLOATS * 4;   // 49152 B

// order-preserving float -> uint, and inverse
__device__ __forceinline__ unsigned ordu(float x) {
    unsigned u = __float_as_uint(x);
    return (u & 0x80000000u) ? ~u : (u | 0x80000000u);
}
__device__ __forceinline__ float iordu(unsigned v) {
    unsigned u = (v & 0x80000000u) ? (v ^ 0x80000000u) : ~v;
    return __uint_as_float(u);
}

// ---------------- packed f32x2 primitives (lanewise IEEE fp32) -------------
typedef unsigned long long ull;

__device__ __forceinline__ ull pack2(float lo, float hi) {
    ull d; asm("mov.b64 %0, {%1, %2};" : "=l"(d) : "f"(lo), "f"(hi)); return d;
}
__device__ __forceinline__ void unpack2(ull v, float& lo, float& hi) {
    asm("mov.b64 {%0, %1}, %2;" : "=f"(lo), "=f"(hi) : "l"(v));
}
__device__ __forceinline__ ull fma2(ull a, ull b, ull c) {
    ull d; asm("fma.rn.f32x2 %0, %1, %2, %3;" : "=l"(d) : "l"(a), "l"(b), "l"(c)); return d;
}
__device__ __forceinline__ ull mul2(ull a, ull b) {
    ull d; asm("mul.rn.f32x2 %0, %1, %2;" : "=l"(d) : "l"(a), "l"(b)); return d;
}
__device__ __forceinline__ ull add2(ull a, ull b) {
    ull d; asm("add.rn.f32x2 %0, %1, %2;" : "=l"(d) : "l"(a), "l"(b)); return d;
}

// B smem row layout: per-tx pad to 10 floats -> 16 distinct banks for the
// 16 tx groups (10*tx mod 32 all distinct), 8B-aligned pairs for LDS.64.
constexpr int BROW = 160;   // 16 tx-groups * 10 floats
__device__ __forceinline__ int bswz(int n) { return (n >> 3) * 10 + (n & 7); }

// ---------------------------------------------------------------------------
// Shared SGEMM body (VERBATIM round-8 best): C = A[M,512] @ W[512,512]^T + bias.
// f32x2 packed FMA inner loop; per-element arithmetic (values and order)
// IDENTICAL to the scalar two-level version of rounds 2-7.
// 256 threads, 8x8 per thread, 128x128 tile at (m0, n0).
// ---------------------------------------------------------------------------
__device__ __forceinline__ void gemm_body(
    const float* __restrict__ A, const float* __restrict__ W,
    const float* __restrict__ bias, float* __restrict__ C,
    int L, int head_major, int m0, int n0)
{
    __shared__ __align__(16) float AsD[2][8][256];   // duplicated A: 16 KB
    __shared__ __align__(16) float Bs [2][8][BROW];  // padded B: 10 KB

    const int t  = threadIdx.x;
    const int tx = t & 15;
    const int ty = t >> 4;
    const int lr = t >> 1;
    const int lc = (t & 1) << 2;

    const float* Ap = A + (size_t)(m0 + lr) * DM_ + lc;
    const float* Wp = W + (size_t)(n0 + lr) * DM_ + lc;
    const int bofs = bswz(lr);

    // prologue: stage k-tile 0 into buffer 0
    {
        float4 av = *(const float4*)(Ap);
        float4 wv = *(const float4*)(Wp);
        ((ull*)AsD[0][lc+0])[lr] = pack2(av.x, av.x);
        ((ull*)AsD[0][lc+1])[lr] = pack2(av.y, av.y);
        ((ull*)AsD[0][lc+2])[lr] = pack2(av.z, av.z);
        ((ull*)AsD[0][lc+3])[lr] = pack2(av.w, av.w);
        Bs[0][lc+0][bofs] = wv.x;
        Bs[0][lc+1][bofs] = wv.y;
        Bs[0][lc+2][bofs] = wv.z;
        Bs[0][lc+3][bofs] = wv.w;
    }
    __syncthreads();

    ull acc2[8][4];
    #pragma unroll
    for (int i = 0; i < 8; i++)
        #pragma unroll
        for (int j = 0; j < 4; j++) acc2[i][j] = pack2(0.f, 0.f);

    #pragma unroll 1
    for (int k0 = 0; k0 < DM_; k0 += 8) {
        const int  p    = (k0 >> 3) & 1;
        const bool more = (k0 + 8) < DM_;
        float4 av, wv;
        if (more) {
            av = *(const float4*)(Ap + k0 + 8);
            wv = *(const float4*)(Wp + k0 + 8);
        }

        ull cacc2[8][4];
        #pragma unroll
        for (int k = 0; k < 8; k++) {
            // a (duplicated) : 8 ull = 4x LDS.128 broadcast
            ull a2[8];
            {
                const ulonglong2* ar = (const ulonglong2*)&AsD[p][k][0];
                #pragma unroll
                for (int ii = 0; ii < 4; ii++) {
                    ulonglong2 v = ar[ty*4 + ii];
                    a2[2*ii]   = v.x;
                    a2[2*ii+1] = v.y;
                }
            }
            // b pairs: 4x LDS.64, conflict-free via 10-float padding
            ull b2[4];
            {
                const ull* br = (const ull*)&Bs[p][k][tx*10];
                #pragma unroll
                for (int j = 0; j < 4; j++) b2[j] = br[j];
            }
            if (k == 0) {
                #pragma unroll
                for (int i = 0; i < 8; i++)
                    #pragma unroll
                    for (int j = 0; j < 4; j++)
                        cacc2[i][j] = mul2(a2[i], b2[j]);
            } else {
                #pragma unroll
                for (int i = 0; i < 8; i++)
                    #pragma unroll
                    for (int j = 0; j < 4; j++)
                        cacc2[i][j] = fma2(a2[i], b2[j], cacc2[i][j]);
            }
        }
        #pragma unroll
        for (int i = 0; i < 8; i++)
            #pragma unroll
            for (int j = 0; j < 4; j++)
                acc2[i][j] = add2(acc2[i][j], cacc2[i][j]);

        if (more) {
            const int q = p ^ 1;
            ((ull*)AsD[q][lc+0])[lr] = pack2(av.x, av.x);
            ((ull*)AsD[q][lc+1])[lr] = pack2(av.y, av.y);
            ((ull*)AsD[q][lc+2])[lr] = pack2(av.z, av.z);
            ((ull*)AsD[q][lc+3])[lr] = pack2(av.w, av.w);
            Bs[q][lc+0][bofs] = wv.x;
            Bs[q][lc+1][bofs] = wv.y;
            Bs[q][lc+2][bofs] = wv.z;
            Bs[q][lc+3][bofs] = wv.w;
        }
        __syncthreads();
    }

    #pragma unroll
    for (int i = 0; i < 8; i++) {
        int m  = m0 + ty*8 + i;
        int bb_ = m / L;
        int l   = m - bb_ * L;
        #pragma unroll
        for (int j = 0; j < 4; j++) {
            float lo, hi;
            unpack2(acc2[i][j], lo, hi);
            int n0j = n0 + tx*8 + 2*j;
            float v0 = lo + bias[n0j];
            float v1 = hi + bias[n0j + 1];
            if (head_major) {
                int hh0 = n0j >> 6, dk0 = n0j & 63;
                int hh1 = (n0j+1) >> 6, dk1 = (n0j+1) & 63;
                C[((size_t)(bb_*H_ + hh0) * L + l) * DK_ + dk0] = v0;
                C[((size_t)(bb_*H_ + hh1) * L + l) * DK_ + dk1] = v1;
            } else {
                C[(size_t)m * DM_ + n0j]     = v0;
                C[(size_t)m * DM_ + n0j + 1] = v1;
            }
        }
    }
}

// Merged Q/K/V projection: grid (64 + 256 + 256, 4).
__global__ void __launch_bounds__(256, 1)
qkv_gemm_kernel(const float* __restrict__ q_in, const float* __restrict__ k_in,
                const float* __restrict__ v_in,
                const float* __restrict__ Wq, const float* __restrict__ bq,
                const float* __restrict__ Wk, const float* __restrict__ bk,
                const float* __restrict__ Wv, const float* __restrict__ bv,
                float* __restrict__ pq, float* __restrict__ pk, float* __restrict__ pv)
{
    const int bx = blockIdx.x;
    const float *A, *W, *bias; float* C; int L, mblk;
    if (bx < 64)        { A = q_in; W = Wq; bias = bq; C = pq; L = LQ_; mblk = bx; }
    else if (bx < 320)  { A = k_in; W = Wk; bias = bk; C = pk; L = LM_; mblk = bx - 64; }
    else                { A = v_in; W = Wv; bias = bv; C = pv; L = LM_; mblk = bx - 320; }
    gemm_body(A, W, bias, C, L, 1, mblk * 128, blockIdx.y * 128);
}

// Output projection: plain row-major.
__global__ void __launch_bounds__(256, 1)
out_gemm_kernel(const float* __restrict__ A, const float* __restrict__ W,
                const float* __restrict__ bias, float* __restrict__ C)
{
    gemm_body(A, W, bias, C, LQ_, 0, blockIdx.x * 128, blockIdx.y * 128);
}

// ---------------------------------------------------------------------------
// Fused scores + EXACT top-32 + softmax + V gather — round-14 structure with
// QT=64: warp owns 8 rows (4 query row-pairs), so each per-lane K load feeds
// 4 row-pairs instead of 2. K crossbar bytes per query HALVE (the binding
// resource per round-15's post-mortem), staging traffic per query halves.
// Per-(q,k) contraction is the round-14 statement verbatim with identical
// operand values => scores bit-identical (rel_err 8.774736e-4). Selection
// algorithm and per-row sub-ascending visit order verbatim rounds 13-14.
// ---------------------------------------------------------------------------
__global__ void __launch_bounds__(256, 2)
attn_topk_kernel(const float* __restrict__ gq, const float* __restrict__ gk,
                 const float* __restrict__ gv, float* __restrict__ gx)
{
    extern __shared__ float sm[];
    ull*   qp = (ull*)(sm + OFF_QP);   // 32 rp x 64 dims, f32x2 packed
    float* ks = sm + OFF_KS;           // xor-swizzled float4 K tile

    const int t    = threadIdx.x;
    const int lane = t & 31;
    const int w    = t >> 5;               // warp id; owns rows 8w..8w+7
    const int qt0  = blockIdx.x * QT;
    const int h    = blockIdx.y;
    const int b    = blockIdx.z;
    const unsigned FULL = 0xffffffffu;

    // ---- pack Q row-pairs into smem (once per block) ----
    const float* qbase = gq + ((size_t)(b*H_ + h) * LQ_ + qt0) * DK_;
    #pragma unroll
    for (int i = t; i < (QT/2)*DK_; i += 256) {
        int rp = i >> 6, d = i & 63;
        float lo = qbase[(size_t)(2*rp)   * DK_ + d];
        float hi = qbase[(size_t)(2*rp+1) * DK_ + d];
        qp[i] = pack2(lo, hi);
    }

    const float* kbase = gk + (size_t)(b*H_ + h) * LM_ * DK_;

    // running top-32 state for the eight rows owned by this warp
    unsigned bval[8] = {0u,0u,0u,0u,0u,0u,0u,0u};
    int      bidx[8] = {0,0,0,0,0,0,0,0};
    unsigned m[8]    = {0u,0u,0u,0u,0u,0u,0u,0u};

    // this lane's 4 key indices within a chunk (sub*32 + lane)
    const int key0 = lane;
    const int key1 = 32 + lane;
    const int key2 = 64 + lane;
    const int key3 = 96 + lane;

    // this warp's four query row-pairs (rows 8w..8w+7)
    const ull* qrpB = qp + (4*w) * DK_;

    #pragma unroll 1
    for (int c0 = 0; c0 < LM_; c0 += CK) {
        __syncthreads();  // all warps done reading ks of previous chunk
                          // (also covers qp prep on first iteration)

        // ---- stage K chunk (CK x 64) with XOR swizzle: conflict-free ----
        #pragma unroll
        for (int i = t; i < CK*16; i += 256) {
            int row = i >> 4, col = i & 15;
            float4 v4 = ((const float4*)(kbase + (size_t)(c0 + row) * DK_))[col];
            ((float4*)ks)[(row << 4) | (col ^ (row & 15))] = v4;
        }
        __syncthreads();

        // ---- scores in f32x2 registers: 4 keys x 4 row-pairs ----
        ull acc2[4][4];   // [sub][rp]
        #pragma unroll
        for (int sub = 0; sub < 4; sub++)
            #pragma unroll
            for (int rp = 0; rp < 4; rp++) acc2[sub][rp] = pack2(0.f, 0.f);

        {
            const float4* ks4 = (const float4*)ks;
            #pragma unroll 4
            for (int d4 = 0; d4 < DK_/4; d4++) {
                float4 kv0 = ks4[(key0 << 4) | (d4 ^ (key0 & 15))];
                float4 kv1 = ks4[(key1 << 4) | (d4 ^ (key1 & 15))];
                float4 kv2 = ks4[(key2 << 4) | (d4 ^ (key2 & 15))];
                float4 kv3 = ks4[(key3 << 4) | (d4 ^ (key3 & 15))];

                ull kx[4], ky[4], kz[4], kw[4];
                kx[0]=pack2(kv0.x,kv0.x); ky[0]=pack2(kv0.y,kv0.y);
                kz[0]=pack2(kv0.z,kv0.z); kw[0]=pack2(kv0.w,kv0.w);
                kx[1]=pack2(kv1.x,kv1.x); ky[1]=pack2(kv1.y,kv1.y);
                kz[1]=pack2(kv1.z,kv1.z); kw[1]=pack2(kv1.w,kv1.w);
                kx[2]=pack2(kv2.x,kv2.x); ky[2]=pack2(kv2.y,kv2.y);
                kz[2]=pack2(kv2.z,kv2.z); kw[2]=pack2(kv2.w,kv2.w);
                kx[3]=pack2(kv3.x,kv3.x); ky[3]=pack2(kv3.y,kv3.y);
                kz[3]=pack2(kv3.z,kv3.z); kw[3]=pack2(kv3.w,kv3.w);

                #pragma unroll
                for (int rp = 0; rp < 4; rp++) {
                    ulonglong2 qa = *(const ulonglong2*)(qrpB + rp*DK_ + d4*4);
                    ulonglong2 qb = *(const ulonglong2*)(qrpB + rp*DK_ + d4*4 + 2);
                    #pragma unroll
                    for (int sub = 0; sub < 4; sub++) {
                        ull tt = mul2(kx[sub], qa.x);
                        tt = fma2(ky[sub], qa.y, tt);
                        tt = fma2(kz[sub], qb.x, tt);
                        tt = fma2(kw[sub], qb.y, tt);
                        acc2[sub][rp] = add2(acc2[sub][rp], tt);
                    }
                }
            }
        }

        // ---- select on register scores, row r = 2*rp + half ----
        #pragma unroll 1
        for (int r = 0; r < 8; r++) {
            const int rp   = r >> 1;
            const int half = r & 1;
            float f0a, f0b, f1a, f1b, f2a, f2b, f3a, f3b;
            unpack2(acc2[0][rp], f0a, f0b);
            unpack2(acc2[1][rp], f1a, f1b);
            unpack2(acc2[2][rp], f2a, f2b);
            unpack2(acc2[3][rp], f3a, f3b);
            unsigned u0 = ordu((half ? f0b : f0a) * 0.125f);   // 1/sqrt(64)
            unsigned u1 = ordu((half ? f1b : f1a) * 0.125f);
            unsigned u2 = ordu((half ? f2b : f2a) * 0.125f);
            unsigned u3 = ordu((half ? f3b : f3a) * 0.125f);

            if (c0 != 0) {
                // fast path: skip row if nothing exceeds m[r] (exact: m is
                // monotone non-decreasing, so skipping is equivalent).
                bool any = (u0 > m[r]) | (u1 > m[r]) | (u2 > m[r]) | (u3 > m[r]);
                if (__ballot_sync(FULL, any) == 0u) continue;
            }

            #pragma unroll 1
            for (int sub = 0; sub < 4; sub++) {
                unsigned u = (sub == 0) ? u0 : (sub == 1) ? u1 : (sub == 2) ? u2 : u3;
                const int i0 = c0 + sub*32;

                if (c0 == 0 && sub == 0) {          // initial fill
                    bval[r] = u; bidx[r] = lane;
                    m[r] = __reduce_min_sync(FULL, bval[r]);
                    continue;
                }

                unsigned hit = __ballot_sync(FULL, u > m[r]);
                while (hit) {                        // warp-uniform rare path
                    int s = __ffs(hit) - 1; hit &= hit - 1;
                    unsigned uc = __shfl_sync(FULL, u, s);
                    if (uc > m[r]) {                 // recheck vs updated m
                        int ic = i0 + s;
                        unsigned em = __ballot_sync(FULL, bval[r] == m[r]);
                        int el;
                        if (__popc(em) > 1) {
                            // tie on min: evict LARGER index (jax keeps lower)
                            int cb = ((em >> lane) & 1) ? bidx[r] : -1;
                            int mx = __reduce_max_sync(FULL, cb);
                            el = __ffs(__ballot_sync(FULL,
                                    (bval[r] == m[r]) && (bidx[r] == mx))) - 1;
                        } else {
                            el = __ffs(em) - 1;
                        }
                        if (lane == el) { bval[r] = uc; bidx[r] = ic; }
                        m[r] = __reduce_min_sync(FULL, bval[r]);
                    }
                }
            }
        }
    }

    // ---- softmax + weighted V gather for the eight rows ----
    const float* vbase = gv + (size_t)(b*H_ + h) * LM_ * DK_;
    #pragma unroll 1
    for (int rr = 0; rr < 8; rr++) {
        float v  = iordu(bval[rr]);
        float mx = v;
        #pragma unroll
        for (int off = 16; off; off >>= 1)
            mx = fmaxf(mx, __shfl_xor_sync(FULL, mx, off));
        float e = __expf(v - mx);
        float s = e;
        #pragma unroll
        for (int off = 16; off; off >>= 1)
            s += __shfl_xor_sync(FULL, s, off);
        float wgt = e / s;

        float a0 = 0.f, a1 = 0.f;
        #pragma unroll 4
        for (int it = 0; it < TOPK_; it++) {
            float wi = __shfl_sync(FULL, wgt, it);
            int   ki = __shfl_sync(FULL, bidx[rr], it);
            const float* vr = vbase + (size_t)ki * DK_;
            a0 = fmaf(wi, vr[lane],      a0);
            a1 = fmaf(wi, vr[lane + 32], a1);
        }
        float* orow = gx + ((size_t)b * LQ_ + (qt0 + 8*w + rr)) * DM_ + h*DK_;
        orow[lane]      = a0;
        orow[lane + 32] = a1;
    }
}

// ---------------------------------------------------------------------------
extern "C" void kernel_launch(void* const* d_in, const int* in_sizes, int n_in,
                              void* d_out, int out_size)
{
    const float* query = (const float*)d_in[0];
    const float* key   = (const float*)d_in[1];
    const float* value = (const float*)d_in[2];
    const float* Wq    = (const float*)d_in[3];
    const float* bq    = (const float*)d_in[4];
    const float* Wk    = (const float*)d_in[5];
    const float* bk    = (const float*)d_in[6];
    const float* Wv    = (const float*)d_in[7];
    const float* bv    = (const float*)d_in[8];
    const float* Wo    = (const float*)d_in[9];
    const float* bo    = (const float*)d_in[10];
    float* out = (float*)d_out;

    float *pq, *pk, *pv, *px;
    cudaGetSymbolAddress((void**)&pq, g_q);
    cudaGetSymbolAddress((void**)&pk, g_k);
    cudaGetSymbolAddress((void**)&pv, g_v);
    cudaGetSymbolAddress((void**)&px, g_x);

    cudaFuncSetAttribute(attn_topk_kernel,
                         cudaFuncAttributeMaxDynamicSharedMemorySize, SMEM_BYTES);

    // merged Q/K/V projections into head-major scratch (round-8 geometry)
    qkv_gemm_kernel<<<dim3(576, DM_/128), 256>>>(query, key, value,
                                                 Wq, bq, Wk, bk, Wv, bv,
                                                 pq, pk, pv);

    // fused scores + topk + softmax + gather (64 queries per block)
    attn_topk_kernel<<<dim3(LQ_/QT, H_, B_), 256, SMEM_BYTES>>>(pq, pk, pv, px);

    // output projection (plain row-major)
    out_gemm_kernel<<<dim3(B_*LQ_/128, DM_/128), 256>>>(px, Wo, bo, out);
}

// round 17
// speedup vs baseline: 1.1289x; 1.1289x over previous
#include <cuda_runtime.h>
#include <cstdint>

// Problem constants
constexpr int B_   = 8;
constexpr int H_   = 8;
constexpr int LQ_  = 1024;
constexpr int LM_  = 4096;
constexpr int DM_  = 512;
constexpr int DK_  = 64;
constexpr int TOPK_ = 32;

// Attention kernel tiling
constexpr int QT   = 32;    // queries per block (4 rows per warp)
constexpr int CK   = 64;    // key chunk (double-buffered, 16 KB each)
constexpr int NCH  = LM_ / CK;   // 64 chunks

// Scratch (static device arrays: allocation-free)
__device__ float g_q[B_*H_*LQ_*DK_];   // 16 MB  [B,H,LQ,Dk]
__device__ float g_k[B_*H_*LM_*DK_];   // 64 MB  [B,H,LM,Dk]
__device__ float g_v[B_*H_*LM_*DK_];   // 64 MB  [B,H,LM,Dk]
__device__ float g_x[B_*LQ_*DM_];      // 16 MB  [B,LQ,DM] pre-output-proj

// ---------------- attention smem layout (float units) ----------------------
// qp: 16 row-pairs x 64 dims, f32x2 packed (1024 ull = 8 KB)
// ks: DOUBLE-BUFFERED K chunk, 2 x (64 x 64) floats, xor-swizzled float4
constexpr int OFF_QP  = 0;                  // 2048 floats (1024 ull)
constexpr int OFF_KS  = OFF_QP + 2048;      // 2 x 4096 floats
constexpr int SMEM_FLOATS = OFF_KS + 2*CK*DK_;
constexpr int SMEM_BYTES  = SMEM_FLOATS * 4;   // 40960 B -> 3 blocks/SM

// order-preserving float -> uint, and inverse
__device__ __forceinline__ unsigned ordu(float x) {
    unsigned u = __float_as_uint(x);
    return (u & 0x80000000u) ? ~u : (u | 0x80000000u);
}
__device__ __forceinline__ float iordu(unsigned v) {
    unsigned u = (v & 0x80000000u) ? (v ^ 0x80000000u) : ~v;
    return __uint_as_float(u);
}

// ---------------- packed f32x2 primitives (lanewise IEEE fp32) -------------
typedef unsigned long long ull;

__device__ __forceinline__ ull pack2(float lo, float hi) {
    ull d; asm("mov.b64 %0, {%1, %2};" : "=l"(d) : "f"(lo), "f"(hi)); return d;
}
__device__ __forceinline__ void unpack2(ull v, float& lo, float& hi) {
    asm("mov.b64 {%0, %1}, %2;" : "=f"(lo), "=f"(hi) : "l"(v));
}
__device__ __forceinline__ ull fma2(ull a, ull b, ull c) {
    ull d; asm("fma.rn.f32x2 %0, %1, %2, %3;" : "=l"(d) : "l"(a), "l"(b), "l"(c)); return d;
}
__device__ __forceinline__ ull mul2(ull a, ull b) {
    ull d; asm("mul.rn.f32x2 %0, %1, %2;" : "=l"(d) : "l"(a), "l"(b)); return d;
}
__device__ __forceinline__ ull add2(ull a, ull b) {
    ull d; asm("add.rn.f32x2 %0, %1, %2;" : "=l"(d) : "l"(a), "l"(b)); return d;
}

// cp.async 16-byte copy (global -> shared), sm_80+ / sm_103a LDGSTS
__device__ __forceinline__ void cp16(unsigned dst_smem, const void* src) {
    asm volatile("cp.async.ca.shared.global [%0], [%1], 16;"
                 :: "r"(dst_smem), "l"(src));
}

// B smem row layout: per-tx pad to 10 floats -> 16 distinct banks for the
// 16 tx groups (10*tx mod 32 all distinct), 8B-aligned pairs for LDS.64.
constexpr int BROW = 160;   // 16 tx-groups * 10 floats
__device__ __forceinline__ int bswz(int n) { return (n >> 3) * 10 + (n & 7); }

// ---------------------------------------------------------------------------
// Shared SGEMM body (VERBATIM round-8 best): C = A[M,512] @ W[512,512]^T + bias.
// f32x2 packed FMA inner loop; per-element arithmetic (values and order)
// IDENTICAL to the scalar two-level version of rounds 2-7.
// 256 threads, 8x8 per thread, 128x128 tile at (m0, n0).
// ---------------------------------------------------------------------------
__device__ __forceinline__ void gemm_body(
    const float* __restrict__ A, const float* __restrict__ W,
    const float* __restrict__ bias, float* __restrict__ C,
    int L, int head_major, int m0, int n0)
{
    __shared__ __align__(16) float AsD[2][8][256];   // duplicated A: 16 KB
    __shared__ __align__(16) float Bs [2][8][BROW];  // padded B: 10 KB

    const int t  = threadIdx.x;
    const int tx = t & 15;
    const int ty = t >> 4;
    const int lr = t >> 1;
    const int lc = (t & 1) << 2;

    const float* Ap = A + (size_t)(m0 + lr) * DM_ + lc;
    const float* Wp = W + (size_t)(n0 + lr) * DM_ + lc;
    const int bofs = bswz(lr);

    // prologue: stage k-tile 0 into buffer 0
    {
        float4 av = *(const float4*)(Ap);
        float4 wv = *(const float4*)(Wp);
        ((ull*)AsD[0][lc+0])[lr] = pack2(av.x, av.x);
        ((ull*)AsD[0][lc+1])[lr] = pack2(av.y, av.y);
        ((ull*)AsD[0][lc+2])[lr] = pack2(av.z, av.z);
        ((ull*)AsD[0][lc+3])[lr] = pack2(av.w, av.w);
        Bs[0][lc+0][bofs] = wv.x;
        Bs[0][lc+1][bofs] = wv.y;
        Bs[0][lc+2][bofs] = wv.z;
        Bs[0][lc+3][bofs] = wv.w;
    }
    __syncthreads();

    ull acc2[8][4];
    #pragma unroll
    for (int i = 0; i < 8; i++)
        #pragma unroll
        for (int j = 0; j < 4; j++) acc2[i][j] = pack2(0.f, 0.f);

    #pragma unroll 1
    for (int k0 = 0; k0 < DM_; k0 += 8) {
        const int  p    = (k0 >> 3) & 1;
        const bool more = (k0 + 8) < DM_;
        float4 av, wv;
        if (more) {
            av = *(const float4*)(Ap + k0 + 8);
            wv = *(const float4*)(Wp + k0 + 8);
        }

        ull cacc2[8][4];
        #pragma unroll
        for (int k = 0; k < 8; k++) {
            // a (duplicated) : 8 ull = 4x LDS.128 broadcast
            ull a2[8];
            {
                const ulonglong2* ar = (const ulonglong2*)&AsD[p][k][0];
                #pragma unroll
                for (int ii = 0; ii < 4; ii++) {
                    ulonglong2 v = ar[ty*4 + ii];
                    a2[2*ii]   = v.x;
                    a2[2*ii+1] = v.y;
                }
            }
            // b pairs: 4x LDS.64, conflict-free via 10-float padding
            ull b2[4];
            {
                const ull* br = (const ull*)&Bs[p][k][tx*10];
                #pragma unroll
                for (int j = 0; j < 4; j++) b2[j] = br[j];
            }
            if (k == 0) {
                #pragma unroll
                for (int i = 0; i < 8; i++)
                    #pragma unroll
                    for (int j = 0; j < 4; j++)
                        cacc2[i][j] = mul2(a2[i], b2[j]);
            } else {
                #pragma unroll
                for (int i = 0; i < 8; i++)
                    #pragma unroll
                    for (int j = 0; j < 4; j++)
                        cacc2[i][j] = fma2(a2[i], b2[j], cacc2[i][j]);
            }
        }
        #pragma unroll
        for (int i = 0; i < 8; i++)
            #pragma unroll
            for (int j = 0; j < 4; j++)
                acc2[i][j] = add2(acc2[i][j], cacc2[i][j]);

        if (more) {
            const int q = p ^ 1;
            ((ull*)AsD[q][lc+0])[lr] = pack2(av.x, av.x);
            ((ull*)AsD[q][lc+1])[lr] = pack2(av.y, av.y);
            ((ull*)AsD[q][lc+2])[lr] = pack2(av.z, av.z);
            ((ull*)AsD[q][lc+3])[lr] = pack2(av.w, av.w);
            Bs[q][lc+0][bofs] = wv.x;
            Bs[q][lc+1][bofs] = wv.y;
            Bs[q][lc+2][bofs] = wv.z;
            Bs[q][lc+3][bofs] = wv.w;
        }
        __syncthreads();
    }

    #pragma unroll
    for (int i = 0; i < 8; i++) {
        int m  = m0 + ty*8 + i;
        int bb_ = m / L;
        int l   = m - bb_ * L;
        #pragma unroll
        for (int j = 0; j < 4; j++) {
            float lo, hi;
            unpack2(acc2[i][j], lo, hi);
            int n0j = n0 + tx*8 + 2*j;
            float v0 = lo + bias[n0j];
            float v1 = hi + bias[n0j + 1];
            if (head_major) {
                int hh0 = n0j >> 6, dk0 = n0j & 63;
                int hh1 = (n0j+1) >> 6, dk1 = (n0j+1) & 63;
                C[((size_t)(bb_*H_ + hh0) * L + l) * DK_ + dk0] = v0;
                C[((size_t)(bb_*H_ + hh1) * L + l) * DK_ + dk1] = v1;
            } else {
                C[(size_t)m * DM_ + n0j]     = v0;
                C[(size_t)m * DM_ + n0j + 1] = v1;
            }
        }
    }
}

// Merged Q/K/V projection: grid (64 + 256 + 256, 4).
__global__ void __launch_bounds__(256, 1)
qkv_gemm_kernel(const float* __restrict__ q_in, const float* __restrict__ k_in,
                const float* __restrict__ v_in,
                const float* __restrict__ Wq, const float* __restrict__ bq,
                const float* __restrict__ Wk, const float* __restrict__ bk,
                const float* __restrict__ Wv, const float* __restrict__ bv,
                float* __restrict__ pq, float* __restrict__ pk, float* __restrict__ pv)
{
    const int bx = blockIdx.x;
    const float *A, *W, *bias; float* C; int L, mblk;
    if (bx < 64)        { A = q_in; W = Wq; bias = bq; C = pq; L = LQ_; mblk = bx; }
    else if (bx < 320)  { A = k_in; W = Wk; bias = bk; C = pk; L = LM_; mblk = bx - 64; }
    else                { A = v_in; W = Wv; bias = bv; C = pv; L = LM_; mblk = bx - 320; }
    gemm_body(A, W, bias, C, L, 1, mblk * 128, blockIdx.y * 128);
}

// Output projection: plain row-major.
__global__ void __launch_bounds__(256, 1)
out_gemm_kernel(const float* __restrict__ A, const float* __restrict__ W,
                const float* __restrict__ bias, float* __restrict__ C)
{
    gemm_body(A, W, bias, C, LQ_, 0, blockIdx.x * 128, blockIdx.y * 128);
}

// ---------------------------------------------------------------------------
// Fused scores + EXACT top-32 + softmax + V gather — round-14 arithmetic and
// selection (bit-identical) with cp.async DOUBLE-BUFFERED K staging at CK=64:
//   loop c: issue cp.async(chunk c+1 -> buf[(c+1)&1]); compute chunk c on
//           buf[c&1]; cp.async.wait; ONE __syncthreads per chunk.
// Staging LDG latency is hidden behind a full chunk of compute; STS leaves
// the warp issue stream (LDGSTS). smem 40 KB keeps occupancy 3 (24 warps).
// Per-(q,k) fma2 contraction statement is verbatim round 14 (chunk size does
// not enter it); selection visit order is chunks-ascending x sub-ascending ==
// the same global ascending key order => selection bit-identical
// (rel_err 8.774736e-4).
// ---------------------------------------------------------------------------
__global__ void __launch_bounds__(256, 3)
attn_topk_kernel(const float* __restrict__ gq, const float* __restrict__ gk,
                 const float* __restrict__ gv, float* __restrict__ gx)
{
    extern __shared__ float sm[];
    ull*   qp = (ull*)(sm + OFF_QP);   // 16 rp x 64 dims, f32x2 packed
    float* ks = sm + OFF_KS;           // 2 x (64 x 64) xor-swizzled float4

    const int t    = threadIdx.x;
    const int lane = t & 31;
    const int w    = t >> 5;               // warp id; owns rows 4w..4w+3
    const int qt0  = blockIdx.x * QT;
    const int h    = blockIdx.y;
    const int b    = blockIdx.z;
    const unsigned FULL = 0xffffffffu;

    // ---- pack Q row-pairs into smem (once per block) ----
    const float* qbase = gq + ((size_t)(b*H_ + h) * LQ_ + qt0) * DK_;
    #pragma unroll
    for (int i = t; i < (QT/2)*DK_; i += 256) {
        int rp = i >> 6, d = i & 63;
        float lo = qbase[(size_t)(2*rp)   * DK_ + d];
        float hi = qbase[(size_t)(2*rp+1) * DK_ + d];
        qp[i] = pack2(lo, hi);
    }

    const float* kbase = gk + (size_t)(b*H_ + h) * LM_ * DK_;
    const unsigned ksb = (unsigned)__cvta_generic_to_shared(ks);

    // async-stage chunk cidx into buffer (cidx & 1); 4 cp.asyncs per thread
    auto stage = [&](int cidx) {
        const int c0 = cidx * CK;
        const unsigned base = ksb + (unsigned)((cidx & 1) * (CK*DK_*4));
        #pragma unroll
        for (int i = t; i < CK*16; i += 256) {
            int row = i >> 4, col = i & 15;
            unsigned dst = base + (unsigned)((((row << 4) | (col ^ (row & 15))) << 4));
            cp16(dst, kbase + (size_t)(c0 + row) * DK_ + col*4);
        }
        asm volatile("cp.async.commit_group;");
    };

    // running top-32 state for the four rows owned by this warp
    unsigned bval[4] = {0u, 0u, 0u, 0u};
    int      bidx[4] = {0, 0, 0, 0};
    unsigned m[4]    = {0u, 0u, 0u, 0u};

    // this lane's 2 key indices within a chunk (sub*32 + lane)
    const int key0 = lane;
    const int key1 = 32 + lane;

    // this warp's two query row-pairs (rows 4w..4w+3)
    const ull* qrp0 = qp + (2*w)     * DK_;
    const ull* qrp1 = qp + (2*w + 1) * DK_;

    // prologue: stage chunk 0
    stage(0);
    asm volatile("cp.async.wait_group 0;" ::: "memory");
    __syncthreads();

    #pragma unroll 1
    for (int c = 0; c < NCH; c++) {
        const int c0 = c * CK;
        if (c + 1 < NCH) stage(c + 1);   // overlaps with compute below

        // ---- scores in f32x2 registers: 2 keys x 2 row-pairs ----
        ull acc2[2][2];   // [sub][rp]
        acc2[0][0] = pack2(0.f, 0.f); acc2[0][1] = pack2(0.f, 0.f);
        acc2[1][0] = pack2(0.f, 0.f); acc2[1][1] = pack2(0.f, 0.f);

        {
            const float4* ks4 = (const float4*)(ks + (c & 1) * (CK*DK_));
            #pragma unroll 4
            for (int d4 = 0; d4 < DK_/4; d4++) {
                float4 kv0 = ks4[(key0 << 4) | (d4 ^ (key0 & 15))];
                float4 kv1 = ks4[(key1 << 4) | (d4 ^ (key1 & 15))];

                ull kx0 = pack2(kv0.x,kv0.x), ky0 = pack2(kv0.y,kv0.y);
                ull kz0 = pack2(kv0.z,kv0.z), kw0 = pack2(kv0.w,kv0.w);
                ull kx1 = pack2(kv1.x,kv1.x), ky1 = pack2(kv1.y,kv1.y);
                ull kz1 = pack2(kv1.z,kv1.z), kw1 = pack2(kv1.w,kv1.w);

                ulonglong2 qa0 = *(const ulonglong2*)(qrp0 + d4*4);
                ulonglong2 qb0 = *(const ulonglong2*)(qrp0 + d4*4 + 2);
                ulonglong2 qa1 = *(const ulonglong2*)(qrp1 + d4*4);
                ulonglong2 qb1 = *(const ulonglong2*)(qrp1 + d4*4 + 2);

                ull t00 = mul2(kx0, qa0.x);
                t00 = fma2(ky0, qa0.y, t00);
                t00 = fma2(kz0, qb0.x, t00);
                t00 = fma2(kw0, qb0.y, t00);
                acc2[0][0] = add2(acc2[0][0], t00);

                ull t01 = mul2(kx0, qa1.x);
                t01 = fma2(ky0, qa1.y, t01);
                t01 = fma2(kz0, qb1.x, t01);
                t01 = fma2(kw0, qb1.y, t01);
                acc2[0][1] = add2(acc2[0][1], t01);

                ull t10 = mul2(kx1, qa0.x);
                t10 = fma2(ky1, qa0.y, t10);
                t10 = fma2(kz1, qb0.x, t10);
                t10 = fma2(kw1, qb0.y, t10);
                acc2[1][0] = add2(acc2[1][0], t10);

                ull t11 = mul2(kx1, qa1.x);
                t11 = fma2(ky1, qa1.y, t11);
                t11 = fma2(kz1, qb1.x, t11);
                t11 = fma2(kw1, qb1.y, t11);
                acc2[1][1] = add2(acc2[1][1], t11);
            }
        }

        // ---- select on register scores, row r = 2*rp + half ----
        #pragma unroll 1
        for (int r = 0; r < 4; r++) {
            const int rp   = r >> 1;
            const int half = r & 1;
            float f0a, f0b, f1a, f1b;
            unpack2(acc2[0][rp], f0a, f0b);
            unpack2(acc2[1][rp], f1a, f1b);
            unsigned u0 = ordu((half ? f0b : f0a) * 0.125f);   // 1/sqrt(64)
            unsigned u1 = ordu((half ? f1b : f1a) * 0.125f);

            if (c0 != 0) {
                // fast path: skip row if nothing exceeds m[r] (exact: m is
                // monotone non-decreasing, so skipping is equivalent).
                bool any = (u0 > m[r]) | (u1 > m[r]);
                if (__ballot_sync(FULL, any) == 0u) continue;
            }

            #pragma unroll 1
            for (int sub = 0; sub < 2; sub++) {
                unsigned u = sub ? u1 : u0;
                const int i0 = c0 + sub*32;

                if (c0 == 0 && sub == 0) {          // initial fill
                    bval[r] = u; bidx[r] = lane;
                    m[r] = __reduce_min_sync(FULL, bval[r]);
                    continue;
                }

                unsigned hit = __ballot_sync(FULL, u > m[r]);
                while (hit) {                        // warp-uniform rare path
                    int s = __ffs(hit) - 1; hit &= hit - 1;
                    unsigned uc = __shfl_sync(FULL, u, s);
                    if (uc > m[r]) {                 // recheck vs updated m
                        int ic = i0 + s;
                        unsigned em = __ballot_sync(FULL, bval[r] == m[r]);
                        int el;
                        if (__popc(em) > 1) {
                            // tie on min: evict LARGER index (jax keeps lower)
                            int cb = ((em >> lane) & 1) ? bidx[r] : -1;
                            int mx = __reduce_max_sync(FULL, cb);
                            el = __ffs(__ballot_sync(FULL,
                                    (bval[r] == m[r]) && (bidx[r] == mx))) - 1;
                        } else {
                            el = __ffs(em) - 1;
                        }
                        if (lane == el) { bval[r] = uc; bidx[r] = ic; }
                        m[r] = __reduce_min_sync(FULL, bval[r]);
                    }
                }
            }
        }

        if (c + 1 < NCH)
            asm volatile("cp.async.wait_group 0;" ::: "memory");
        __syncthreads();
    }

    // ---- softmax + weighted V gather for the four rows ----
    const float* vbase = gv + (size_t)(b*H_ + h) * LM_ * DK_;
    #pragma unroll 1
    for (int rr = 0; rr < 4; rr++) {
        float v  = iordu(bval[rr]);
        float mx = v;
        #pragma unroll
        for (int off = 16; off; off >>= 1)
            mx = fmaxf(mx, __shfl_xor_sync(FULL, mx, off));
        float e = __expf(v - mx);
        float s = e;
        #pragma unroll
        for (int off = 16; off; off >>= 1)
            s += __shfl_xor_sync(FULL, s, off);
        float wgt = e / s;

        float a0 = 0.f, a1 = 0.f;
        #pragma unroll 4
        for (int it = 0; it < TOPK_; it++) {
            float wi = __shfl_sync(FULL, wgt, it);
            int   ki = __shfl_sync(FULL, bidx[rr], it);
            const float* vr = vbase + (size_t)ki * DK_;
            a0 = fmaf(wi, vr[lane],      a0);
            a1 = fmaf(wi, vr[lane + 32], a1);
        }
        float* orow = gx + ((size_t)b * LQ_ + (qt0 + 4*w + rr)) * DM_ + h*DK_;
        orow[lane]      = a0;
        orow[lane + 32] = a1;
    }
}

// ---------------------------------------------------------------------------
extern "C" void kernel_launch(void* const* d_in, const int* in_sizes, int n_in,
                              void* d_out, int out_size)
{
    const float* query = (const float*)d_in[0];
    const float* key   = (const float*)d_in[1];
    const float* value = (const float*)d_in[2];
    const float* Wq    = (const float*)d_in[3];
    const float* bq    = (const float*)d_in[4];
    const float* Wk    = (const float*)d_in[5];
    const float* bk    = (const float*)d_in[6];
    const float* Wv    = (const float*)d_in[7];
    const float* bv    = (const float*)d_in[8];
    const float* Wo    = (const float*)d_in[9];
    const float* bo    = (const float*)d_in[10];
    float* out = (float*)d_out;

    float *pq, *pk, *pv, *px;
    cudaGetSymbolAddress((void**)&pq, g_q);
    cudaGetSymbolAddress((void**)&pk, g_k);
    cudaGetSymbolAddress((void**)&pv, g_v);
    cudaGetSymbolAddress((void**)&px, g_x);

    cudaFuncSetAttribute(attn_topk_kernel,
                         cudaFuncAttributeMaxDynamicSharedMemorySize, SMEM_BYTES);

    // merged Q/K/V projections into head-major scratch (round-8 geometry)
    qkv_gemm_kernel<<<dim3(576, DM_/128), 256>>>(query, key, value,
                                                 Wq, bq, Wk, bk, Wv, bv,
                                                 pq, pk, pv);

    // fused scores + topk + softmax + gather
    attn_topk_kernel<<<dim3(LQ_/QT, H_, B_), 256, SMEM_BYTES>>>(pq, pk, pv, px);

    // output projection (plain row-major)
    out_gemm_kernel<<<dim3(B_*LQ_/128, DM_/128), 256>>>(px, Wo, bo, out);
}